// round 15
// baseline (speedup 1.0000x reference)
#include <cuda_runtime.h>
#include <math.h>

// ---------------- problem constants ----------------
#define B_      4
#define T_      8192
#define D_      1024
#define NBLK    64
#define LBLK    128
#define NTOPK   16
#define NMACRO  4
#define LMACRO  2048
#define NS      21
#define MROWS   84
#define F2D     2048
#define RMS_EPS 1.1920929e-07f

// ---------------- scratch ----------------
__device__ __align__(16) float g_blockmean[B_ * NBLK * D_];
__device__ __align__(16) float g_hidp[B_ * NBLK * 2];
__device__ __align__(16) float g_feats[MROWS * F2D];
__device__ __align__(16) float g_part1[16 * MROWS * D_];
__device__ __align__(16) float g_partK[8 * MROWS * D_];
__device__ __align__(16) float g_partV[8 * MROWS * D_];
__device__ __align__(16) float g_partO[16 * MROWS * D_];
__device__ __align__(16) float g_spre[MROWS * D_];
__device__ __align__(16) float g_ssq[MROWS * 8];
__device__ __align__(16) float g_keys[MROWS * D_];
__device__ __align__(16) float g_ovals[MROWS * D_];

// ---------------- helpers ----------------
__device__ __forceinline__ float4 f4add(float4 a, float4 b) {
    return make_float4(a.x + b.x, a.y + b.y, a.z + b.z, a.w + b.w);
}
__device__ __forceinline__ float4 f4scale(float4 a, float s) {
    return make_float4(a.x * s, a.y * s, a.z * s, a.w * s);
}
__device__ __forceinline__ void ffma2(unsigned long long& d,
                                      unsigned long long a,
                                      unsigned long long b) {
    asm("fma.rn.f32x2 %0, %1, %2, %0;" : "+l"(d) : "l"(a), "l"(b));
}
__device__ __forceinline__ float acc_sum(unsigned long long v) {
    unsigned int lo, hi;
    asm("mov.b64 {%0, %1}, %2;" : "=r"(lo), "=r"(hi) : "l"(v));
    return __uint_as_float(lo) + __uint_as_float(hi);
}
__device__ __forceinline__ void cpasync16(unsigned int dst, const void* src) {
    asm volatile("cp.async.cg.shared.global [%0], [%1], 16;" :: "r"(dst), "l"(src));
}
#define CP_COMMIT() asm volatile("cp.async.commit_group;" ::: "memory")
#define CP_WAIT0()  asm volatile("cp.async.wait_group 0;" ::: "memory")
#define CP_WAIT2()  asm volatile("cp.async.wait_group 2;" ::: "memory")

__device__ __forceinline__ void grid_dep_sync() {
#if defined(__CUDA_ARCH__) && (__CUDA_ARCH__ >= 900)
    cudaGridDependencySynchronize();
#endif
}

// ============================================================================
// K1: per-block means + per-half hid-score ssq. grid (256, 2), 128 threads.
// ============================================================================
__global__ void __launch_bounds__(128) scan_kernel(const float* __restrict__ ph) {
    int b   = blockIdx.x >> 6;
    int blk = blockIdx.x & 63;
    int half = blockIdx.y;
    int c   = (half << 9) + (threadIdx.x << 2);
    const float* base = ph + ((size_t)b * T_ + (size_t)blk * LBLK) * D_ + c;

    float4 acc[8];
#pragma unroll
    for (int i = 0; i < 8; i++) acc[i] = make_float4(0.f, 0.f, 0.f, 0.f);

    for (int r = 0; r < LBLK; r += 8) {
#pragma unroll
        for (int i = 0; i < 8; i++) {
            float4 v = *(const float4*)(base + (size_t)(r + i) * D_);
            acc[i].x += v.x; acc[i].y += v.y; acc[i].z += v.z; acc[i].w += v.w;
        }
    }
    float4 s = acc[0];
#pragma unroll
    for (int i = 1; i < 8; i++) s = f4add(s, acc[i]);
    s = f4scale(s, 1.f / LBLK);
    *(float4*)(g_blockmean + (size_t)(b * NBLK + blk) * D_ + c) = s;

    float ss = s.x * s.x + s.y * s.y + s.z * s.z + s.w * s.w;
    int w = threadIdx.x >> 5, l = threadIdx.x & 31;
#pragma unroll
    for (int o = 16; o; o >>= 1) ss += __shfl_xor_sync(0xffffffffu, ss, o);
    __shared__ float red[4];
    if (l == 0) red[w] = ss;
    __syncthreads();
    if (threadIdx.x == 0)
        g_hidp[(b * NBLK + blk) * 2 + half] = red[0] + red[1] + red[2] + red[3];
}

// ============================================================================
// K2: scoring + top-k + feats build, fused. grid (NS, B_), 256 threads.
// ============================================================================
__global__ void __launch_bounds__(256) score_feats_kernel(
    const float* __restrict__ ph, const float* __restrict__ nll)
{
    int s = blockIdx.x, b = blockIdx.y;
    int tid = threadIdx.x, w = tid >> 5, l = tid & 31;
    __shared__ float hid[NBLK];
    __shared__ float sur[NBLK];
    __shared__ int   ch[NTOPK];

    grid_dep_sync();   // needs g_blockmean / g_hidp from scan

    if (s < NTOPK) {
        if (tid < NBLK)
            hid[tid] = sqrtf(g_hidp[(b * NBLK + tid) * 2]
                           + g_hidp[(b * NBLK + tid) * 2 + 1]);
        for (int j = 0; j < 8; j++) {
            int blk = w * 8 + j;
            float4 nv = *(const float4*)(nll + (size_t)b * T_ + blk * LBLK + l * 4);
            float ns = nv.x + nv.y + nv.z + nv.w;
#pragma unroll
            for (int o = 16; o; o >>= 1) ns += __shfl_xor_sync(0xffffffffu, ns, o);
            if (l == 0) sur[blk] = ns * (1.f / LBLK);
        }
        __syncthreads();

        if (tid == 0) {
            float mh = 0.f, ms = 0.f;
            for (int i = 0; i < NBLK; i++) { mh += hid[i]; ms += sur[i]; }
            mh *= (1.f / NBLK); ms *= (1.f / NBLK);
            float vh = 0.f, vs = 0.f;
            for (int i = 0; i < NBLK; i++) {
                float a = hid[i] - mh; float c2 = sur[i] - ms;
                vh += a * a; vs += c2 * c2;
            }
            float sh  = fmaxf(sqrtf(vh * (1.f / NBLK)), 1e-6f);
            float ss2 = fmaxf(sqrtf(vs * (1.f / NBLK)), 1e-6f);

            float sc[NBLK];
            for (int i = 0; i < NBLK; i++)
                sc[i] = (hid[i] - mh) / sh + (sur[i] - ms) / ss2;

            bool used[NBLK] = {};
            int lc[NTOPK];
            for (int k = 0; k < NTOPK; k++) {
                int best = 0; float bv = -1e30f;
                for (int i = 0; i < NBLK; i++)
                    if (!used[i] && sc[i] > bv) { bv = sc[i]; best = i; }
                used[best] = true; lc[k] = best;
            }
            for (int k = 1; k < NTOPK; k++) {
                int v = lc[k], j = k - 1;
                while (j >= 0 && lc[j] > v) { lc[j + 1] = lc[j]; j--; }
                lc[j + 1] = v;
            }
            for (int k = 0; k < NTOPK; k++) ch[k] = lc[k];
        }
        __syncthreads();
    }

    int c = tid << 2;
    float4 mv;
    const float* lastrow;
    if (s < NTOPK) {
        int blk = ch[s];
        mv = *(const float4*)(g_blockmean + (size_t)(b * NBLK + blk) * D_ + c);
        lastrow = ph + ((size_t)b * T_ + (size_t)blk * LBLK + (LBLK - 1)) * D_;
    } else if (s < NTOPK + NMACRO) {
        int m = s - NTOPK;
        float4 acc = make_float4(0.f, 0.f, 0.f, 0.f);
#pragma unroll
        for (int j = 0; j < 16; j++)
            acc = f4add(acc, *(const float4*)(g_blockmean + (size_t)(b * NBLK + m * 16 + j) * D_ + c));
        mv = f4scale(acc, 1.f / 16.f);
        lastrow = ph + ((size_t)b * T_ + (size_t)(m + 1) * LMACRO - 1) * D_;
    } else {
        float4 acc = make_float4(0.f, 0.f, 0.f, 0.f);
        for (int j = 0; j < NBLK; j++)
            acc = f4add(acc, *(const float4*)(g_blockmean + (size_t)(b * NBLK + j) * D_ + c));
        mv = f4scale(acc, 1.f / NBLK);
        lastrow = ph + ((size_t)b * T_ + T_ - 1) * D_;
    }
    float* f = g_feats + (size_t)(b * NS + s) * F2D;
    *(float4*)(f + c)      = mv;
    *(float4*)(f + D_ + c) = *(const float4*)(lastrow + c);
}

// ============================================================================
// 3-stage pipelined NT GEMM (pure-copy A; used by gemm1/gemm2).
// C[M,N] = A[M,K]*B[N,K]^T. BM=32, BN=128, BK=32, 256 thr, dyn smem 60 KB,
// 3 CTAs/SM. Both tiles via cp.async into XOR-quad-swizzled K-major layout.
// Per iter: wait_group 2 (two tiles in flight) -> load latency ~fully hidden.
// mode 2: RMS scale applied at EPILOGUE (C[m,*] *= rsqrt(sum ssq[m]/D+eps)) —
// algebraically identical to scaling A rows. PDL: B stage-0 issued pre-sync.
// ============================================================================
#define PIPE_SMEM_FLOATS (3 * 1024 + 3 * 4096)
#define PIPE_SMEM_BYTES  (PIPE_SMEM_FLOATS * 4)

__global__ void __launch_bounds__(256, 3) gemm_pipe_kernel(
    const float* __restrict__ A,
    const float* __restrict__ B0, float* __restrict__ C0,
    const float* __restrict__ B1, float* __restrict__ C1,
    int M, int N, int K, int Kc, int nx0, int mode)
{
    extern __shared__ __align__(16) float smem[];
    int xt = blockIdx.x;
    const float* Bp = B0; float* Cp = C0;
    if (xt >= nx0) { Bp = B1; Cp = C1; xt -= nx0; }
    int m0 = blockIdx.y * 32;
    int n0 = xt * 128;
    int k0 = blockIdx.z * Kc;
    Cp += (size_t)blockIdx.z * M * N;

    int tid = threadIdx.x;
    int w = tid >> 5, l = tid & 31;
    int lk = tid & 7;
    int ln = tid >> 3;

    unsigned int sbase = (unsigned int)__cvta_generic_to_shared(smem);
    int aoff = ln * 32 + ((lk ^ (ln >> 2)) << 2);
    int boff = ln * 32 + ((lk ^ (ln & 7)) << 2);
    unsigned int adst[3], bdst[3];
#pragma unroll
    for (int s = 0; s < 3; s++) {
        adst[s] = sbase + ((s * 1024 + aoff) << 2);
        bdst[s] = sbase + ((3072 + s * 4096 + boff) << 2);
    }
    const float* bsrc = Bp + (size_t)(n0 + ln) * K + k0 + (lk << 2);
    int am = min(m0 + ln, M - 1);
    const float* asrc = A + (size_t)am * K + k0 + (lk << 2);

    int mr  = (l >> 3) + ((w >> 2) << 2);
    int nb  = (l & 7) + ((w & 3) << 3);
    int nb7 = nb & 7;

    unsigned long long acc[4][4];
#pragma unroll
    for (int j = 0; j < 4; j++)
#pragma unroll
        for (int i = 0; i < 4; i++) acc[j][i] = 0ull;

    int nIter = Kc >> 5;

    // B stage 0 (weights — independent of upstream): issue before PDL sync
#pragma unroll
    for (int i = 0; i < 4; i++)
        cpasync16(bdst[0] + (i << 12), bsrc + (size_t)(i << 5) * K);

    grid_dep_sync();

    // epilogue row scales (mode 2)
    float scR[4] = {1.f, 1.f, 1.f, 1.f};
    if (mode == 2) {
#pragma unroll
        for (int j = 0; j < 4; j++) {
            int m = min(m0 + (mr << 2) + j, M - 1);
            float ssum = 0.f;
#pragma unroll
            for (int i = 0; i < 8; i++) ssum += g_ssq[m * 8 + i];
            scR[j] = rsqrtf(ssum * (1.f / D_) + RMS_EPS);
        }
    }

    // A stage 0, commit group 0
    cpasync16(adst[0], asrc);
    CP_COMMIT();
    // stage 1, commit group 1
    if (nIter > 1) {
#pragma unroll
        for (int i = 0; i < 4; i++)
            cpasync16(bdst[1] + (i << 12), bsrc + 32 + (size_t)(i << 5) * K);
        cpasync16(adst[1], asrc + 32);
    }
    CP_COMMIT();

    for (int it = 0; it < nIter; it++) {
        int cur = it % 3;
        if (it + 2 < nIter) {
            int s = (it + 2) % 3;
            const float* bs2 = bsrc + (it + 2) * 32;
            const float* as2 = asrc + (it + 2) * 32;
#pragma unroll
            for (int i = 0; i < 4; i++)
                cpasync16(bdst[s] + (i << 12), bs2 + (size_t)(i << 5) * K);
            cpasync16(adst[s], as2);
            CP_COMMIT();
            CP_WAIT2();
        } else {
            CP_WAIT0();
        }
        __syncthreads();

        const float* Ac = smem + cur * 1024;
        const float* Bc = smem + 3072 + cur * 4096;
#pragma unroll
        for (int kq = 0; kq < 8; kq++) {
            int bo = (kq ^ nb7) << 2;
            int ao = (kq ^ mr) << 2;
            ulonglong2 b[4];
#pragma unroll
            for (int i = 0; i < 4; i++)
                b[i] = *(const ulonglong2*)(Bc + (nb + (i << 5)) * 32 + bo);
#pragma unroll
            for (int j = 0; j < 4; j++) {
                ulonglong2 a = *(const ulonglong2*)(Ac + ((mr << 2) + j) * 32 + ao);
#pragma unroll
                for (int i = 0; i < 4; i++) {
                    ffma2(acc[j][i], a.x, b[i].x);
                    ffma2(acc[j][i], a.y, b[i].y);
                }
            }
        }
        __syncthreads();
    }

#pragma unroll
    for (int j = 0; j < 4; j++) {
        int m = m0 + (mr << 2) + j;
        if (m < M) {
            float* cp = Cp + (size_t)m * N + n0;
#pragma unroll
            for (int i = 0; i < 4; i++)
                cp[nb + (i << 5)] = scR[j] * acc_sum(acc[j][i]);
        }
    }
}

// ============================================================================
// 2-stage NT GEMM with inline A-partial summation (gemm3: A = sum of 8 partV
// slices). Same tiling/swizzles as the pipe kernel. Static smem 40 KB.
// ============================================================================
__global__ void __launch_bounds__(256, 3) gemm_nt_kernel(
    const float* __restrict__ A,
    const float* __restrict__ B0, float* __restrict__ C0,
    const float* __restrict__ B1, float* __restrict__ C1,
    int M, int N, int K, int Kc, int nx0, int aParts, size_t aStride, int mode)
{
    int xt = blockIdx.x;
    const float* Bp = B0; float* Cp = C0;
    if (xt >= nx0) { Bp = B1; Cp = C1; xt -= nx0; }
    int m0 = blockIdx.y * 32;
    int n0 = xt * 128;
    int k0 = blockIdx.z * Kc;
    Cp += (size_t)blockIdx.z * M * N;

    __shared__ __align__(16) float As[2][32 * 32];
    __shared__ __align__(16) float Bs[2][128 * 32];

    int tid = threadIdx.x;
    int w = tid >> 5, l = tid & 31;

    int lk = tid & 7;
    int ln = tid >> 3;
    unsigned int sB0 = (unsigned int)__cvta_generic_to_shared(&Bs[0][0]);
    unsigned int sB1 = (unsigned int)__cvta_generic_to_shared(&Bs[1][0]);
    int bswq = (lk ^ (ln & 7)) << 2;
    unsigned int bdst[2];
    bdst[0] = sB0 + (((ln * 32) + bswq) << 2);
    bdst[1] = sB1 + (((ln * 32) + bswq) << 2);
    const float* bsrc = Bp + (size_t)(n0 + ln) * K + k0 + (lk << 2);
    int am = min(m0 + ln, M - 1);
    const float* asrc = A + (size_t)am * K + k0 + (lk << 2);
    int aoff = ln * 32 + ((lk ^ (ln >> 2)) << 2);

    int mr  = (l >> 3) + ((w >> 2) << 2);
    int nb  = (l & 7) + ((w & 3) << 3);
    int nb7 = nb & 7;

    unsigned long long acc[4][4];
#pragma unroll
    for (int j = 0; j < 4; j++)
#pragma unroll
        for (int i = 0; i < 4; i++) acc[j][i] = 0ull;

#pragma unroll
    for (int i = 0; i < 4; i++)
        cpasync16(bdst[0] + (i << 12), bsrc + (size_t)(i << 5) * K);
    CP_COMMIT();

    grid_dep_sync();

    float scA = 1.f;
    if (mode == 2) {
        float ssum = 0.f;
#pragma unroll
        for (int i = 0; i < 8; i++) ssum += g_ssq[am * 8 + i];
        scA = rsqrtf(ssum * (1.f / D_) + RMS_EPS);
    }

    float4 a0 = *(const float4*)asrc;
    for (int p = 1; p < aParts; p++)
        a0 = f4add(a0, *(const float4*)(asrc + (size_t)p * aStride));
    if (mode == 2) a0 = f4scale(a0, scA);
    *(float4*)&As[0][aoff] = a0;
    CP_WAIT0();
    __syncthreads();

    int nIter = Kc >> 5;
    for (int it = 0; it < nIter; it++) {
        int cur = it & 1, nxt = cur ^ 1;
        bool more = (it + 1 < nIter);
        if (more) {
            bsrc += 32; asrc += 32;
#pragma unroll
            for (int i = 0; i < 4; i++)
                cpasync16(bdst[nxt] + (i << 12), bsrc + (size_t)(i << 5) * K);
            CP_COMMIT();
            a0 = *(const float4*)asrc;
            for (int p = 1; p < aParts; p++)
                a0 = f4add(a0, *(const float4*)(asrc + (size_t)p * aStride));
            if (mode == 2) a0 = f4scale(a0, scA);
        }

        const float* Ac = &As[cur][0];
        const float* Bc = &Bs[cur][0];
#pragma unroll
        for (int kq = 0; kq < 8; kq++) {
            int bo = (kq ^ nb7) << 2;
            int ao = (kq ^ mr) << 2;
            ulonglong2 b[4];
#pragma unroll
            for (int i = 0; i < 4; i++)
                b[i] = *(const ulonglong2*)(Bc + (nb + (i << 5)) * 32 + bo);
#pragma unroll
            for (int j = 0; j < 4; j++) {
                ulonglong2 a = *(const ulonglong2*)(Ac + ((mr << 2) + j) * 32 + ao);
#pragma unroll
                for (int i = 0; i < 4; i++) {
                    ffma2(acc[j][i], a.x, b[i].x);
                    ffma2(acc[j][i], a.y, b[i].y);
                }
            }
        }

        if (more) {
            *(float4*)&As[nxt][aoff] = a0;
            CP_WAIT0();
        }
        __syncthreads();
    }

#pragma unroll
    for (int j = 0; j < 4; j++) {
        int m = m0 + (mr << 2) + j;
        if (m < M) {
            float* cp = Cp + (size_t)m * N + n0;
#pragma unroll
            for (int i = 0; i < 4; i++)
                cp[nb + (i << 5)] = acc_sum(acc[j][i]);
        }
    }
}

// ============================================================================
// Reduce 16 gemm1 partials: grid (MROWS, 8)=672 CTAs, 128 thr.
// ============================================================================
__global__ void __launch_bounds__(128) reduce_ssq_kernel() {
    int m = blockIdx.x, oct = blockIdx.y;
    int col4 = threadIdx.x & 31, grp = threadIdx.x >> 5;
    int c = (oct << 7) + (col4 << 2);
    const float* base = g_part1 + (size_t)m * D_ + c
                      + (size_t)(grp * 4) * MROWS * D_;

    grid_dep_sync();   // needs g_part1 from gemm1

    float4 acc = make_float4(0.f, 0.f, 0.f, 0.f);
#pragma unroll
    for (int s = 0; s < 4; s++)
        acc = f4add(acc, *(const float4*)(base + (size_t)s * MROWS * D_));

    __shared__ __align__(16) float4 buf[3][32];
    if (grp) buf[grp - 1][col4] = acc;
    __syncthreads();
    if (grp == 0) {
        acc = f4add(acc, buf[0][col4]);
        acc = f4add(acc, buf[1][col4]);
        acc = f4add(acc, buf[2][col4]);
        *(float4*)(g_spre + (size_t)m * D_ + c) = acc;

        float ss = acc.x * acc.x + acc.y * acc.y + acc.z * acc.z + acc.w * acc.w;
#pragma unroll
        for (int o = 16; o; o >>= 1) ss += __shfl_xor_sync(0xffffffffu, ss, o);
        if (col4 == 0) g_ssq[m * 8 + oct] = ss;
    }
}

// ============================================================================
// Reduce split-K partials for TWO arrays (parametrized part counts).
// grid (MROWS, 4, 2)=672 CTAs, 128 thr.
// ============================================================================
__global__ void __launch_bounds__(128) reduce_dual_kernel(
    const float* __restrict__ p0, float* __restrict__ o0, int parts0,
    const float* __restrict__ p1, float* __restrict__ o1, int parts1)
{
    const float* p = blockIdx.z ? p1 : p0;
    float*       o = blockIdx.z ? o1 : o0;
    int parts    = blockIdx.z ? parts1 : parts0;
    int m = blockIdx.x;
    int col4 = threadIdx.x & 63, grp = threadIdx.x >> 6;
    int c = (blockIdx.y << 8) + (col4 << 2);
    int half = parts >> 1;
    const float* base = p + (size_t)m * D_ + c
                      + (size_t)(grp * half) * MROWS * D_;

    grid_dep_sync();   // needs partials from gemm2/gemm3

    float4 acc = make_float4(0.f, 0.f, 0.f, 0.f);
    for (int s = 0; s < half; s++)
        acc = f4add(acc, *(const float4*)(base + (size_t)s * MROWS * D_));

    __shared__ __align__(16) float4 buf[64];
    if (grp) buf[col4] = acc;
    __syncthreads();
    if (grp == 0) {
        acc = f4add(acc, buf[col4]);
        *(float4*)(o + (size_t)m * D_ + c) = acc;
    }
}

// ============================================================================
// Fused attention: logits -> softmax -> mix precomputed ovals.
// ============================================================================
__global__ void __launch_bounds__(256) attn_kernel(const float* __restrict__ query,
                                                   float* __restrict__ out) {
    int q = blockIdx.x, b = blockIdx.y;
    int tid = threadIdx.x, w = tid >> 5, l = tid & 31;
    __shared__ float lg[NS];

    grid_dep_sync();   // needs g_keys / g_ovals

    const float* qrow = query + (size_t)q * D_;
    for (int s = w; s < NS; s += 8) {
        const float* kr = g_keys + (size_t)(b * NS + s) * D_;
        float p = 0.f;
#pragma unroll
        for (int i = 0; i < 8; i++) {
            float4 qa = *(const float4*)(qrow + ((i << 5) + l) * 4);
            float4 ka = *(const float4*)(kr + ((i << 5) + l) * 4);
            p = fmaf(qa.x, ka.x, p);
            p = fmaf(qa.y, ka.y, p);
            p = fmaf(qa.z, ka.z, p);
            p = fmaf(qa.w, ka.w, p);
        }
#pragma unroll
        for (int o = 16; o; o >>= 1) p += __shfl_xor_sync(0xffffffffu, p, o);
        if (l == 0) lg[s] = p * (1.f / 32.f);
    }
    __syncthreads();

    float mx = -1e30f;
#pragma unroll
    for (int s = 0; s < NS; s++) mx = fmaxf(mx, lg[s]);
    float e[NS];
    float sum = 0.f;
#pragma unroll
    for (int s = 0; s < NS; s++) { e[s] = __expf(lg[s] - mx); sum += e[s]; }
    float inv = 1.f / sum;

    int c = tid << 2;
    float4 o4 = make_float4(0.f, 0.f, 0.f, 0.f);
#pragma unroll
    for (int s = 0; s < NS; s++) {
        float a = e[s] * inv;
        float4 v = *(const float4*)(g_ovals + (size_t)(b * NS + s) * D_ + c);
        o4.x = fmaf(a, v.x, o4.x);
        o4.y = fmaf(a, v.y, o4.y);
        o4.z = fmaf(a, v.z, o4.z);
        o4.w = fmaf(a, v.w, o4.w);
    }
    *(float4*)(out + (size_t)(b * 64 + q) * D_ + c) = o4;
}

// ============================================================================
// launch — all nodes with ProgrammaticStreamSerialization (PDL)
// ============================================================================
static inline void pdl_launch(const void* fn, dim3 gd, dim3 bd, void** args,
                              size_t smem = 0) {
    cudaLaunchConfig_t cfg = {};
    cfg.gridDim = gd;
    cfg.blockDim = bd;
    cfg.stream = 0;
    cfg.dynamicSmemBytes = smem;
    cudaLaunchAttribute at[1];
    at[0].id = cudaLaunchAttributeProgrammaticStreamSerialization;
    at[0].val.programmaticStreamSerializationAllowed = 1;
    cfg.attrs = at;
    cfg.numAttrs = 1;
    cudaLaunchKernelExC(&cfg, fn, args);
}

extern "C" void kernel_launch(void* const* d_in, const int* in_sizes, int n_in,
                              void* d_out, int out_size) {
    const float* ph    = (const float*)d_in[0];
    const float* nll   = (const float*)d_in[1];
    const float* query = (const float*)d_in[2];
    const float* Wsum  = (const float*)d_in[3];
    const float* Wk    = (const float*)d_in[4];
    const float* Wv    = (const float*)d_in[5];
    const float* Wo    = (const float*)d_in[6];
    float* out = (float*)d_out;

    float *p_feats, *p_part1, *p_partK, *p_partV, *p_partO;
    float *p_spre, *p_keys, *p_ovals;
    cudaGetSymbolAddress((void**)&p_feats, g_feats);
    cudaGetSymbolAddress((void**)&p_part1, g_part1);
    cudaGetSymbolAddress((void**)&p_partK, g_partK);
    cudaGetSymbolAddress((void**)&p_partV, g_partV);
    cudaGetSymbolAddress((void**)&p_partO, g_partO);
    cudaGetSymbolAddress((void**)&p_spre,  g_spre);
    cudaGetSymbolAddress((void**)&p_keys,  g_keys);
    cudaGetSymbolAddress((void**)&p_ovals, g_ovals);

    cudaFuncSetAttribute((const void*)gemm_pipe_kernel,
                         cudaFuncAttributeMaxDynamicSharedMemorySize,
                         PIPE_SMEM_BYTES);

    // 1. block means + hid-score partials
    {
        void* args[] = { (void*)&ph };
        pdl_launch((const void*)scan_kernel, dim3(B_ * NBLK, 2), dim3(128), args);
    }
    // 2. fused scoring + top-k + feature rows
    {
        void* args[] = { (void*)&ph, (void*)&nll };
        pdl_launch((const void*)score_feats_kernel, dim3(NS, B_), dim3(256), args);
    }
    // 3. gemm1 (pipelined): spre partials = feats @ Wsum^T (splitK=16, 384 CTAs)
    {
        int M = MROWS, N = D_, K = F2D, Kc = 128, nx0 = 8, md = 0;
        void* args[] = { (void*)&p_feats, (void*)&Wsum, (void*)&p_part1,
                         (void*)&Wsum, (void*)&p_part1,
                         &M, &N, &K, &Kc, &nx0, &md };
        pdl_launch((const void*)gemm_pipe_kernel, dim3(8, 3, 16), dim3(256), args,
                   PIPE_SMEM_BYTES);
    }
    // 4. reduce gemm1 partials -> spre + per-oct ssq (672 CTAs)
    {
        pdl_launch((const void*)reduce_ssq_kernel, dim3(MROWS, 8), dim3(128), nullptr);
    }
    // 5. gemm2 (pipelined): keys/vals = rms(spre) @ {Wk,Wv}^T (mode 2 epilogue,
    //    splitK=8, 384 CTAs)
    {
        int M = MROWS, N = D_, K = D_, Kc = 128, nx0 = 8, md = 2;
        void* args[] = { (void*)&p_spre, (void*)&Wk, (void*)&p_partK,
                         (void*)&Wv, (void*)&p_partV,
                         &M, &N, &K, &Kc, &nx0, &md };
        pdl_launch((const void*)gemm_pipe_kernel, dim3(16, 3, 8), dim3(256), args,
                   PIPE_SMEM_BYTES);
    }
    // 6. gemm3 (2-stage, inline A-sum): ovals partials = (sum V partials) @ Wo^T
    //    splitK=16 (Kc=64) -> 384 CTAs
    {
        int M = MROWS, N = D_, K = D_, Kc = 64, nx0 = 8, aP = 8, md = 0;
        size_t aS = (size_t)MROWS * D_;
        void* args[] = { (void*)&p_partV, (void*)&Wo, (void*)&p_partO,
                         (void*)&Wo, (void*)&p_partO,
                         &M, &N, &K, &Kc, &nx0, &aP, &aS, &md };
        pdl_launch((const void*)gemm_nt_kernel, dim3(8, 3, 16), dim3(256), args);
    }
    // 7. reduce K partials (8) -> keys AND O partials (16) -> ovals (672 CTAs)
    {
        int pk = 8, po = 16;
        void* args[] = { (void*)&p_partK, (void*)&p_keys, &pk,
                         (void*)&p_partO, (void*)&p_ovals, &po };
        pdl_launch((const void*)reduce_dual_kernel, dim3(MROWS, 4, 2), dim3(128), args);
    }
    // 8. fused logits + softmax + output
    {
        void* args[] = { (void*)&query, (void*)&out };
        pdl_launch((const void*)attn_kernel, dim3(64, B_), dim3(256), args);
    }
}

// round 16
// speedup vs baseline: 1.0831x; 1.0831x over previous
#include <cuda_runtime.h>
#include <math.h>

// ---------------- problem constants ----------------
#define B_      4
#define T_      8192
#define D_      1024
#define NBLK    64
#define LBLK    128
#define NTOPK   16
#define NMACRO  4
#define LMACRO  2048
#define NS      21
#define MROWS   84
#define F2D     2048
#define RMS_EPS 1.1920929e-07f

// ---------------- scratch ----------------
__device__ __align__(16) float g_blockmean[B_ * NBLK * D_];
__device__ __align__(16) float g_hidp[B_ * NBLK * 2];
__device__ __align__(16) float g_feats[MROWS * F2D];
__device__ __align__(16) float g_part1[16 * MROWS * D_];
__device__ __align__(16) float g_partK[8 * MROWS * D_];
__device__ __align__(16) float g_partV[8 * MROWS * D_];
__device__ __align__(16) float g_partO[16 * MROWS * D_];
__device__ __align__(16) float g_spre[MROWS * D_];
__device__ __align__(16) float g_ssq[MROWS * 8];
__device__ __align__(16) float g_keys[MROWS * D_];
__device__ __align__(16) float g_ovals[MROWS * D_];

// ---------------- helpers ----------------
__device__ __forceinline__ float4 f4add(float4 a, float4 b) {
    return make_float4(a.x + b.x, a.y + b.y, a.z + b.z, a.w + b.w);
}
__device__ __forceinline__ float4 f4scale(float4 a, float s) {
    return make_float4(a.x * s, a.y * s, a.z * s, a.w * s);
}
__device__ __forceinline__ void ffma2(unsigned long long& d,
                                      unsigned long long a,
                                      unsigned long long b) {
    asm("fma.rn.f32x2 %0, %1, %2, %0;" : "+l"(d) : "l"(a), "l"(b));
}
__device__ __forceinline__ float acc_sum(unsigned long long v) {
    unsigned int lo, hi;
    asm("mov.b64 {%0, %1}, %2;" : "=r"(lo), "=r"(hi) : "l"(v));
    return __uint_as_float(lo) + __uint_as_float(hi);
}
__device__ __forceinline__ void cpasync16(unsigned int dst, const void* src) {
    asm volatile("cp.async.cg.shared.global [%0], [%1], 16;" :: "r"(dst), "l"(src));
}
#define CP_COMMIT() asm volatile("cp.async.commit_group;" ::: "memory")
#define CP_WAIT0()  asm volatile("cp.async.wait_group 0;" ::: "memory")

__device__ __forceinline__ void grid_dep_sync() {
#if defined(__CUDA_ARCH__) && (__CUDA_ARCH__ >= 900)
    cudaGridDependencySynchronize();
#endif
}

// streaming (evict-first) float4 load — for single-use bulk streams
__device__ __forceinline__ float4 ld_stream4(const float* p) {
    float4 v;
    asm("ld.global.cs.v4.f32 {%0, %1, %2, %3}, [%4];"
        : "=f"(v.x), "=f"(v.y), "=f"(v.z), "=f"(v.w) : "l"(p));
    return v;
}

// ============================================================================
// K1: per-block means + per-half hid-score ssq. grid (256, 2), 128 threads.
// prev_hidden is a 134 MB single-use stream -> ld.cs (evict-first) so it
// doesn't evict the weights/partials the downstream GEMMs keep in L2.
// ============================================================================
__global__ void __launch_bounds__(128) scan_kernel(const float* __restrict__ ph) {
    int b   = blockIdx.x >> 6;
    int blk = blockIdx.x & 63;
    int half = blockIdx.y;
    int c   = (half << 9) + (threadIdx.x << 2);
    const float* base = ph + ((size_t)b * T_ + (size_t)blk * LBLK) * D_ + c;

    float4 acc[8];
#pragma unroll
    for (int i = 0; i < 8; i++) acc[i] = make_float4(0.f, 0.f, 0.f, 0.f);

    for (int r = 0; r < LBLK; r += 8) {
#pragma unroll
        for (int i = 0; i < 8; i++) {
            float4 v = ld_stream4(base + (size_t)(r + i) * D_);
            acc[i].x += v.x; acc[i].y += v.y; acc[i].z += v.z; acc[i].w += v.w;
        }
    }
    float4 s = acc[0];
#pragma unroll
    for (int i = 1; i < 8; i++) s = f4add(s, acc[i]);
    s = f4scale(s, 1.f / LBLK);
    *(float4*)(g_blockmean + (size_t)(b * NBLK + blk) * D_ + c) = s;

    float ss = s.x * s.x + s.y * s.y + s.z * s.z + s.w * s.w;
    int w = threadIdx.x >> 5, l = threadIdx.x & 31;
#pragma unroll
    for (int o = 16; o; o >>= 1) ss += __shfl_xor_sync(0xffffffffu, ss, o);
    __shared__ float red[4];
    if (l == 0) red[w] = ss;
    __syncthreads();
    if (threadIdx.x == 0)
        g_hidp[(b * NBLK + blk) * 2 + half] = red[0] + red[1] + red[2] + red[3];
}

// ============================================================================
// K2: scoring + top-k + feats build, fused. grid (NS, B_), 256 threads.
// ============================================================================
__global__ void __launch_bounds__(256) score_feats_kernel(
    const float* __restrict__ ph, const float* __restrict__ nll)
{
    int s = blockIdx.x, b = blockIdx.y;
    int tid = threadIdx.x, w = tid >> 5, l = tid & 31;
    __shared__ float hid[NBLK];
    __shared__ float sur[NBLK];
    __shared__ int   ch[NTOPK];

    grid_dep_sync();   // needs g_blockmean / g_hidp from scan

    if (s < NTOPK) {
        if (tid < NBLK)
            hid[tid] = sqrtf(g_hidp[(b * NBLK + tid) * 2]
                           + g_hidp[(b * NBLK + tid) * 2 + 1]);
        for (int j = 0; j < 8; j++) {
            int blk = w * 8 + j;
            float4 nv = *(const float4*)(nll + (size_t)b * T_ + blk * LBLK + l * 4);
            float ns = nv.x + nv.y + nv.z + nv.w;
#pragma unroll
            for (int o = 16; o; o >>= 1) ns += __shfl_xor_sync(0xffffffffu, ns, o);
            if (l == 0) sur[blk] = ns * (1.f / LBLK);
        }
        __syncthreads();

        if (tid == 0) {
            float mh = 0.f, ms = 0.f;
            for (int i = 0; i < NBLK; i++) { mh += hid[i]; ms += sur[i]; }
            mh *= (1.f / NBLK); ms *= (1.f / NBLK);
            float vh = 0.f, vs = 0.f;
            for (int i = 0; i < NBLK; i++) {
                float a = hid[i] - mh; float c2 = sur[i] - ms;
                vh += a * a; vs += c2 * c2;
            }
            float sh  = fmaxf(sqrtf(vh * (1.f / NBLK)), 1e-6f);
            float ss2 = fmaxf(sqrtf(vs * (1.f / NBLK)), 1e-6f);

            float sc[NBLK];
            for (int i = 0; i < NBLK; i++)
                sc[i] = (hid[i] - mh) / sh + (sur[i] - ms) / ss2;

            bool used[NBLK] = {};
            int lc[NTOPK];
            for (int k = 0; k < NTOPK; k++) {
                int best = 0; float bv = -1e30f;
                for (int i = 0; i < NBLK; i++)
                    if (!used[i] && sc[i] > bv) { bv = sc[i]; best = i; }
                used[best] = true; lc[k] = best;
            }
            for (int k = 1; k < NTOPK; k++) {
                int v = lc[k], j = k - 1;
                while (j >= 0 && lc[j] > v) { lc[j + 1] = lc[j]; j--; }
                lc[j + 1] = v;
            }
            for (int k = 0; k < NTOPK; k++) ch[k] = lc[k];
        }
        __syncthreads();
    }

    int c = tid << 2;
    float4 mv;
    const float* lastrow;
    if (s < NTOPK) {
        int blk = ch[s];
        mv = *(const float4*)(g_blockmean + (size_t)(b * NBLK + blk) * D_ + c);
        lastrow = ph + ((size_t)b * T_ + (size_t)blk * LBLK + (LBLK - 1)) * D_;
    } else if (s < NTOPK + NMACRO) {
        int m = s - NTOPK;
        float4 acc = make_float4(0.f, 0.f, 0.f, 0.f);
#pragma unroll
        for (int j = 0; j < 16; j++)
            acc = f4add(acc, *(const float4*)(g_blockmean + (size_t)(b * NBLK + m * 16 + j) * D_ + c));
        mv = f4scale(acc, 1.f / 16.f);
        lastrow = ph + ((size_t)b * T_ + (size_t)(m + 1) * LMACRO - 1) * D_;
    } else {
        float4 acc = make_float4(0.f, 0.f, 0.f, 0.f);
        for (int j = 0; j < NBLK; j++)
            acc = f4add(acc, *(const float4*)(g_blockmean + (size_t)(b * NBLK + j) * D_ + c));
        mv = f4scale(acc, 1.f / NBLK);
        lastrow = ph + ((size_t)b * T_ + T_ - 1) * D_;
    }
    float* f = g_feats + (size_t)(b * NS + s) * F2D;
    *(float4*)(f + c)      = mv;
    *(float4*)(f + D_ + c) = *(const float4*)(lastrow + c);
}

// ============================================================================
// NT GEMM, split-K, 2-stage (R14 proven config — the 3-stage variant REGRESSED;
// at 3 CTAs/SM the co-resident CTAs already cover CP_WAIT0 latency).
// C[M,N] = A[M,K]*B[N,K]^T. BM=32, BN=128, BK=32, 256 thr, 3 CTAs/SM.
// XOR-quad swizzle on both tiles. Dual-B via nx0. aParts>1 sums A slices
// inline. mode 2: scale A rows by rsqrt(sum(g_ssq[row][0..7])/D + eps).
// PDL: B stage-0 (weights = harness inputs) issued before grid_dep_sync.
// ============================================================================
__global__ void __launch_bounds__(256, 3) gemm_nt_kernel(
    const float* __restrict__ A,
    const float* __restrict__ B0, float* __restrict__ C0,
    const float* __restrict__ B1, float* __restrict__ C1,
    int M, int N, int K, int Kc, int nx0, int aParts, size_t aStride, int mode)
{
    int xt = blockIdx.x;
    const float* Bp = B0; float* Cp = C0;
    if (xt >= nx0) { Bp = B1; Cp = C1; xt -= nx0; }
    int m0 = blockIdx.y * 32;
    int n0 = xt * 128;
    int k0 = blockIdx.z * Kc;
    Cp += (size_t)blockIdx.z * M * N;

    __shared__ __align__(16) float As[2][32 * 32];
    __shared__ __align__(16) float Bs[2][128 * 32];

    int tid = threadIdx.x;
    int w = tid >> 5, l = tid & 31;

    // ---- loader mapping ----
    int lk = tid & 7;
    int ln = tid >> 3;
    unsigned int sB0 = (unsigned int)__cvta_generic_to_shared(&Bs[0][0]);
    unsigned int sB1 = (unsigned int)__cvta_generic_to_shared(&Bs[1][0]);
    int bswq = (lk ^ (ln & 7)) << 2;
    unsigned int bdst[2];
    bdst[0] = sB0 + (((ln * 32) + bswq) << 2);
    bdst[1] = sB1 + (((ln * 32) + bswq) << 2);
    const float* bsrc = Bp + (size_t)(n0 + ln) * K + k0 + (lk << 2);
    int am = min(m0 + ln, M - 1);
    const float* asrc = A + (size_t)am * K + k0 + (lk << 2);
    int aoff = ln * 32 + ((lk ^ (ln >> 2)) << 2);

    // ---- compute mapping ----
    int mr  = (l >> 3) + ((w >> 2) << 2);
    int nb  = (l & 7) + ((w & 3) << 3);
    int nb7 = nb & 7;

    unsigned long long acc[4][4];
#pragma unroll
    for (int j = 0; j < 4; j++)
#pragma unroll
        for (int i = 0; i < 4; i++) acc[j][i] = 0ull;

    // ---- prologue part 1: B tile 0 (weights — independent of upstream) ----
#pragma unroll
    for (int i = 0; i < 4; i++)
        cpasync16(bdst[0] + (i << 12), bsrc + (size_t)(i << 5) * K);
    CP_COMMIT();

    grid_dep_sync();

    float scA = 1.f;
    if (mode == 2) {
        float ssum = 0.f;
#pragma unroll
        for (int i = 0; i < 8; i++) ssum += g_ssq[am * 8 + i];
        scA = rsqrtf(ssum * (1.f / D_) + RMS_EPS);
    }

    float4 a0 = *(const float4*)asrc;
    for (int p = 1; p < aParts; p++)
        a0 = f4add(a0, *(const float4*)(asrc + (size_t)p * aStride));
    if (mode == 2) a0 = f4scale(a0, scA);
    *(float4*)&As[0][aoff] = a0;
    CP_WAIT0();
    __syncthreads();

    int nIter = Kc >> 5;
    for (int it = 0; it < nIter; it++) {
        int cur = it & 1, nxt = cur ^ 1;
        bool more = (it + 1 < nIter);
        if (more) {
            bsrc += 32; asrc += 32;
#pragma unroll
            for (int i = 0; i < 4; i++)
                cpasync16(bdst[nxt] + (i << 12), bsrc + (size_t)(i << 5) * K);
            CP_COMMIT();
            a0 = *(const float4*)asrc;
            for (int p = 1; p < aParts; p++)
                a0 = f4add(a0, *(const float4*)(asrc + (size_t)p * aStride));
            if (mode == 2) a0 = f4scale(a0, scA);
        }

        const float* Ac = &As[cur][0];
        const float* Bc = &Bs[cur][0];
#pragma unroll
        for (int kq = 0; kq < 8; kq++) {
            int bo = (kq ^ nb7) << 2;
            int ao = (kq ^ mr) << 2;
            ulonglong2 b[4];
#pragma unroll
            for (int i = 0; i < 4; i++)
                b[i] = *(const ulonglong2*)(Bc + (nb + (i << 5)) * 32 + bo);
#pragma unroll
            for (int j = 0; j < 4; j++) {
                ulonglong2 a = *(const ulonglong2*)(Ac + ((mr << 2) + j) * 32 + ao);
#pragma unroll
                for (int i = 0; i < 4; i++) {
                    ffma2(acc[j][i], a.x, b[i].x);
                    ffma2(acc[j][i], a.y, b[i].y);
                }
            }
        }

        if (more) {
            *(float4*)&As[nxt][aoff] = a0;
            CP_WAIT0();
        }
        __syncthreads();
    }

#pragma unroll
    for (int j = 0; j < 4; j++) {
        int m = m0 + (mr << 2) + j;
        if (m < M) {
            float* cp = Cp + (size_t)m * N + n0;
#pragma unroll
            for (int i = 0; i < 4; i++)
                cp[nb + (i << 5)] = acc_sum(acc[j][i]);
        }
    }
}

// ============================================================================
// Reduce 16 gemm1 partials: grid (MROWS, 8)=672 CTAs, 128 thr.
// ============================================================================
__global__ void __launch_bounds__(128) reduce_ssq_kernel() {
    int m = blockIdx.x, oct = blockIdx.y;
    int col4 = threadIdx.x & 31, grp = threadIdx.x >> 5;
    int c = (oct << 7) + (col4 << 2);
    const float* base = g_part1 + (size_t)m * D_ + c
                      + (size_t)(grp * 4) * MROWS * D_;

    grid_dep_sync();   // needs g_part1 from gemm1

    float4 acc = make_float4(0.f, 0.f, 0.f, 0.f);
#pragma unroll
    for (int s = 0; s < 4; s++)
        acc = f4add(acc, *(const float4*)(base + (size_t)s * MROWS * D_));

    __shared__ __align__(16) float4 buf[3][32];
    if (grp) buf[grp - 1][col4] = acc;
    __syncthreads();
    if (grp == 0) {
        acc = f4add(acc, buf[0][col4]);
        acc = f4add(acc, buf[1][col4]);
        acc = f4add(acc, buf[2][col4]);
        *(float4*)(g_spre + (size_t)m * D_ + c) = acc;

        float ss = acc.x * acc.x + acc.y * acc.y + acc.z * acc.z + acc.w * acc.w;
#pragma unroll
        for (int o = 16; o; o >>= 1) ss += __shfl_xor_sync(0xffffffffu, ss, o);
        if (col4 == 0) g_ssq[m * 8 + oct] = ss;
    }
}

// ============================================================================
// Reduce split-K partials for TWO arrays (parametrized part counts).
// grid (MROWS, 4, 2)=672 CTAs, 128 thr.
// ============================================================================
__global__ void __launch_bounds__(128) reduce_dual_kernel(
    const float* __restrict__ p0, float* __restrict__ o0, int parts0,
    const float* __restrict__ p1, float* __restrict__ o1, int parts1)
{
    const float* p = blockIdx.z ? p1 : p0;
    float*       o = blockIdx.z ? o1 : o0;
    int parts    = blockIdx.z ? parts1 : parts0;
    int m = blockIdx.x;
    int col4 = threadIdx.x & 63, grp = threadIdx.x >> 6;
    int c = (blockIdx.y << 8) + (col4 << 2);
    int half = parts >> 1;
    const float* base = p + (size_t)m * D_ + c
                      + (size_t)(grp * half) * MROWS * D_;

    grid_dep_sync();   // needs partials from gemm2/gemm3

    float4 acc = make_float4(0.f, 0.f, 0.f, 0.f);
    for (int s = 0; s < half; s++)
        acc = f4add(acc, *(const float4*)(base + (size_t)s * MROWS * D_));

    __shared__ __align__(16) float4 buf[64];
    if (grp) buf[col4] = acc;
    __syncthreads();
    if (grp == 0) {
        acc = f4add(acc, buf[col4]);
        *(float4*)(o + (size_t)m * D_ + c) = acc;
    }
}

// ============================================================================
// Fused attention: logits -> softmax -> mix precomputed ovals.
// ============================================================================
__global__ void __launch_bounds__(256) attn_kernel(const float* __restrict__ query,
                                                   float* __restrict__ out) {
    int q = blockIdx.x, b = blockIdx.y;
    int tid = threadIdx.x, w = tid >> 5, l = tid & 31;
    __shared__ float lg[NS];

    grid_dep_sync();   // needs g_keys / g_ovals

    const float* qrow = query + (size_t)q * D_;
    for (int s = w; s < NS; s += 8) {
        const float* kr = g_keys + (size_t)(b * NS + s) * D_;
        float p = 0.f;
#pragma unroll
        for (int i = 0; i < 8; i++) {
            float4 qa = *(const float4*)(qrow + ((i << 5) + l) * 4);
            float4 ka = *(const float4*)(kr + ((i << 5) + l) * 4);
            p = fmaf(qa.x, ka.x, p);
            p = fmaf(qa.y, ka.y, p);
            p = fmaf(qa.z, ka.z, p);
            p = fmaf(qa.w, ka.w, p);
        }
#pragma unroll
        for (int o = 16; o; o >>= 1) p += __shfl_xor_sync(0xffffffffu, p, o);
        if (l == 0) lg[s] = p * (1.f / 32.f);
    }
    __syncthreads();

    float mx = -1e30f;
#pragma unroll
    for (int s = 0; s < NS; s++) mx = fmaxf(mx, lg[s]);
    float e[NS];
    float sum = 0.f;
#pragma unroll
    for (int s = 0; s < NS; s++) { e[s] = __expf(lg[s] - mx); sum += e[s]; }
    float inv = 1.f / sum;

    int c = tid << 2;
    float4 o4 = make_float4(0.f, 0.f, 0.f, 0.f);
#pragma unroll
    for (int s = 0; s < NS; s++) {
        float a = e[s] * inv;
        float4 v = *(const float4*)(g_ovals + (size_t)(b * NS + s) * D_ + c);
        o4.x = fmaf(a, v.x, o4.x);
        o4.y = fmaf(a, v.y, o4.y);
        o4.z = fmaf(a, v.z, o4.z);
        o4.w = fmaf(a, v.w, o4.w);
    }
    *(float4*)(out + (size_t)(b * 64 + q) * D_ + c) = o4;
}

// ============================================================================
// launch — all nodes with ProgrammaticStreamSerialization (PDL)
// ============================================================================
static inline void pdl_launch(const void* fn, dim3 gd, dim3 bd, void** args) {
    cudaLaunchConfig_t cfg = {};
    cfg.gridDim = gd;
    cfg.blockDim = bd;
    cfg.stream = 0;
    cudaLaunchAttribute at[1];
    at[0].id = cudaLaunchAttributeProgrammaticStreamSerialization;
    at[0].val.programmaticStreamSerializationAllowed = 1;
    cfg.attrs = at;
    cfg.numAttrs = 1;
    cudaLaunchKernelExC(&cfg, fn, args);
}

extern "C" void kernel_launch(void* const* d_in, const int* in_sizes, int n_in,
                              void* d_out, int out_size) {
    const float* ph    = (const float*)d_in[0];
    const float* nll   = (const float*)d_in[1];
    const float* query = (const float*)d_in[2];
    const float* Wsum  = (const float*)d_in[3];
    const float* Wk    = (const float*)d_in[4];
    const float* Wv    = (const float*)d_in[5];
    const float* Wo    = (const float*)d_in[6];
    float* out = (float*)d_out;

    float *p_feats, *p_part1, *p_partK, *p_partV, *p_partO;
    float *p_spre, *p_keys, *p_ovals;
    cudaGetSymbolAddress((void**)&p_feats, g_feats);
    cudaGetSymbolAddress((void**)&p_part1, g_part1);
    cudaGetSymbolAddress((void**)&p_partK, g_partK);
    cudaGetSymbolAddress((void**)&p_partV, g_partV);
    cudaGetSymbolAddress((void**)&p_partO, g_partO);
    cudaGetSymbolAddress((void**)&p_spre,  g_spre);
    cudaGetSymbolAddress((void**)&p_keys,  g_keys);
    cudaGetSymbolAddress((void**)&p_ovals, g_ovals);

    // 1. block means + hid-score partials
    {
        void* args[] = { (void*)&ph };
        pdl_launch((const void*)scan_kernel, dim3(B_ * NBLK, 2), dim3(128), args);
    }
    // 2. fused scoring + top-k + feature rows
    {
        void* args[] = { (void*)&ph, (void*)&nll };
        pdl_launch((const void*)score_feats_kernel, dim3(NS, B_), dim3(256), args);
    }
    // 3. gemm1: spre partials = feats @ Wsum^T (splitK=16, Kc=128, 384 CTAs)
    {
        int M = MROWS, N = D_, K = F2D, Kc = 128, nx0 = 8, aP = 1, md = 0;
        size_t aS = 0;
        void* args[] = { (void*)&p_feats, (void*)&Wsum, (void*)&p_part1,
                         (void*)&Wsum, (void*)&p_part1,
                         &M, &N, &K, &Kc, &nx0, &aP, &aS, &md };
        pdl_launch((const void*)gemm_nt_kernel, dim3(8, 3, 16), dim3(256), args);
    }
    // 4. reduce gemm1 partials -> spre + per-oct ssq (672 CTAs)
    {
        pdl_launch((const void*)reduce_ssq_kernel, dim3(MROWS, 8), dim3(128), nullptr);
    }
    // 5. gemm2: keys/vals = rms(spre) @ {Wk,Wv}^T (mode 2, splitK=8, 384 CTAs)
    {
        int M = MROWS, N = D_, K = D_, Kc = 128, nx0 = 8, aP = 1, md = 2;
        size_t aS = 0;
        void* args[] = { (void*)&p_spre, (void*)&Wk, (void*)&p_partK,
                         (void*)&Wv, (void*)&p_partV,
                         &M, &N, &K, &Kc, &nx0, &aP, &aS, &md };
        pdl_launch((const void*)gemm_nt_kernel, dim3(16, 3, 8), dim3(256), args);
    }
    // 6. gemm3: ovals partials = (sum of V partials) @ Wo^T
    //    splitK=16 (Kc=64) -> 384 CTAs
    {
        int M = MROWS, N = D_, K = D_, Kc = 64, nx0 = 8, aP = 8, md = 0;
        size_t aS = (size_t)MROWS * D_;
        void* args[] = { (void*)&p_partV, (void*)&Wo, (void*)&p_partO,
                         (void*)&Wo, (void*)&p_partO,
                         &M, &N, &K, &Kc, &nx0, &aP, &aS, &md };
        pdl_launch((const void*)gemm_nt_kernel, dim3(8, 3, 16), dim3(256), args);
    }
    // 7. reduce K partials (8) -> keys AND O partials (16) -> ovals (672 CTAs)
    {
        int pk = 8, po = 16;
        void* args[] = { (void*)&p_partK, (void*)&p_keys, &pk,
                         (void*)&p_partO, (void*)&p_ovals, &po };
        pdl_launch((const void*)reduce_dual_kernel, dim3(MROWS, 4, 2), dim3(128), args);
    }
    // 8. fused logits + softmax + output
    {
        void* args[] = { (void*)&query, (void*)&out };
        pdl_launch((const void*)attn_kernel, dim3(64, B_), dim3(256), args);
    }
}